// round 1
// baseline (speedup 1.0000x reference)
#include <cuda_runtime.h>
#include <math.h>

#define HID 2048
#define SEQ 2048
#define NH  16
#define HD  128
#define BATCH 2
#define M_ROWS (BATCH*SEQ)   // 4096

// Scratch (allocation-free rule: __device__ globals)
__device__ float g_q[(size_t)M_ROWS * HID];
__device__ float g_k[(size_t)M_ROWS * HID];
__device__ float g_v[(size_t)M_ROWS * HID];
__device__ float g_ctx[(size_t)M_ROWS * HID];

// ---------------------------------------------------------------------------
// 128x128x8 SGEMM, 256 threads, 8x8 register tile.
// Epilogue: + bias, optional RoPE (pairs are within a thread's 4-col groups).
// ---------------------------------------------------------------------------
__device__ __forceinline__ void gemm_body(
    const float* __restrict__ X, const float* __restrict__ W,
    const float* __restrict__ bias, float* __restrict__ Y,
    int M, int N, int K, int rope)
{
    __shared__ float As[8][128];
    __shared__ float Bs[8][128];

    const int tid = threadIdx.x;
    const int tx = tid & 15, ty = tid >> 4;
    const int bm = blockIdx.y * 128, bn = blockIdx.x * 128;

    float acc[8][8];
#pragma unroll
    for (int i = 0; i < 8; i++)
#pragma unroll
        for (int j = 0; j < 8; j++) acc[i][j] = 0.0f;

    const int arow = tid >> 1, acol = (tid & 1) * 4;
    const int brow = tid >> 5, bcol = (tid & 31) * 4;
    const float* Ap = X + (size_t)(bm + arow) * K + acol;
    const float* Bp = W + (size_t)brow * N + bn + bcol;

    for (int k0 = 0; k0 < K; k0 += 8) {
        float4 av = *(const float4*)Ap;
        float4 bv = *(const float4*)Bp;
        Ap += 8;
        Bp += (size_t)8 * N;
        __syncthreads();
        As[acol + 0][arow] = av.x;
        As[acol + 1][arow] = av.y;
        As[acol + 2][arow] = av.z;
        As[acol + 3][arow] = av.w;
        *(float4*)&Bs[brow][bcol] = bv;
        __syncthreads();
#pragma unroll
        for (int kk = 0; kk < 8; kk++) {
            float a[8], b[8];
            *(float4*)&a[0] = *(const float4*)&As[kk][ty * 4];
            *(float4*)&a[4] = *(const float4*)&As[kk][64 + ty * 4];
            *(float4*)&b[0] = *(const float4*)&Bs[kk][tx * 4];
            *(float4*)&b[4] = *(const float4*)&Bs[kk][64 + tx * 4];
#pragma unroll
            for (int i = 0; i < 8; i++)
#pragma unroll
                for (int j = 0; j < 8; j++)
                    acc[i][j] = fmaf(a[i], b[j], acc[i][j]);
        }
    }

    // epilogue: bias (+ optional RoPE), float4 stores
#pragma unroll
    for (int ih = 0; ih < 2; ih++) {
#pragma unroll
        for (int ii = 0; ii < 4; ii++) {
            const int m = bm + ih * 64 + ty * 4 + ii;
            const int s = m & (SEQ - 1);
#pragma unroll
            for (int jh = 0; jh < 2; jh++) {
                const int n = bn + jh * 64 + tx * 4;
                float4 r;
                r.x = acc[ih * 4 + ii][jh * 4 + 0] + bias[n + 0];
                r.y = acc[ih * 4 + ii][jh * 4 + 1] + bias[n + 1];
                r.z = acc[ih * 4 + ii][jh * 4 + 2] + bias[n + 2];
                r.w = acc[ih * 4 + ii][jh * 4 + 3] + bias[n + 3];
                if (rope) {
                    const int d0 = n & (HD - 1);
                    const double j0 = (double)(d0 >> 1);
                    // inv_freq = 10000^(-2j/128); -2*ln(1e4)/128
                    const double kf = -0.14391156831212787;
                    double f0 = exp(kf * j0);
                    double f1 = exp(kf * (j0 + 1.0));
                    double sd, cd;
                    sincos((double)s * f0, &sd, &cd);
                    float s0 = (float)sd, c0 = (float)cd;
                    sincos((double)s * f1, &sd, &cd);
                    float s1 = (float)sd, c1 = (float)cd;
                    float e = r.x, o = r.y;
                    r.x = e * c0 - o * s0;
                    r.y = o * c0 + e * s0;
                    e = r.z; o = r.w;
                    r.z = e * c1 - o * s1;
                    r.w = o * c1 + e * s1;
                }
                *(float4*)&Y[(size_t)m * N + n] = r;
            }
        }
    }
}

__global__ void __launch_bounds__(256) gemm_qkv_kernel(
    const float* __restrict__ X,
    const float* __restrict__ Wq, const float* __restrict__ bq,
    const float* __restrict__ Wk, const float* __restrict__ bk,
    const float* __restrict__ Wv, const float* __restrict__ bv,
    float* __restrict__ q, float* __restrict__ k, float* __restrict__ v)
{
    const float* W;
    const float* b;
    float* Y;
    int rope;
    if (blockIdx.z == 0)      { W = Wq; b = bq; Y = q; rope = 1; }
    else if (blockIdx.z == 1) { W = Wk; b = bk; Y = k; rope = 1; }
    else                      { W = Wv; b = bv; Y = v; rope = 0; }
    gemm_body(X, W, b, Y, M_ROWS, HID, HID, rope);
}

__global__ void __launch_bounds__(256) gemm_out_kernel(
    const float* __restrict__ X, const float* __restrict__ W,
    const float* __restrict__ b, float* __restrict__ Y)
{
    gemm_body(X, W, b, Y, M_ROWS, HID, HID, 0);
}

// ---------------------------------------------------------------------------
// Flash attention, fp32. Br=Bc=64, HD=128. 256 threads (16x16).
// Q/K stored transposed in smem: [HD][64]; V natural [64][HD]; P padded [64][65].
// Thread owns rows ty*4..+3; score cols tx*4..+3; O cols {tx*4, 64+tx*4}.
// ---------------------------------------------------------------------------
#define FL_SMEM ((HD*64 + HD*64 + 64*HD + 64*65) * sizeof(float))

__global__ void __launch_bounds__(256) flash_kernel(
    const float* __restrict__ Qg, const float* __restrict__ Kg,
    const float* __restrict__ Vg, float* __restrict__ Og)
{
    extern __shared__ float sm[];
    float* Qs = sm;              // [HD][64]
    float* Ks = Qs + HD * 64;    // [HD][64]
    float* Vs = Ks + HD * 64;    // [64][HD]
    float* Ps = Vs + 64 * HD;    // [64][65]

    const int tid = threadIdx.x;
    const int tx = tid & 15, ty = tid >> 4;
    const int bh = blockIdx.y;
    const int b = bh / NH, h = bh % NH;
    const int q0 = blockIdx.x * 64;
    const size_t rowbase = (size_t)b * SEQ;
    const int coff = h * HD;

    // load Q tile transposed + pre-scaled
    {
        const int r = tid >> 2;
        const int dgb = (tid & 3) * 4;
        const float* src = Qg + (rowbase + q0 + r) * HID + coff;
        const float sc = 0.08838834764831845f;   // 1/sqrt(128)
#pragma unroll
        for (int dd = 0; dd < 8; dd++) {
            const int d0 = dgb + dd * 16;
            float4 v = *(const float4*)(src + d0);
            Qs[(d0 + 0) * 64 + r] = v.x * sc;
            Qs[(d0 + 1) * 64 + r] = v.y * sc;
            Qs[(d0 + 2) * 64 + r] = v.z * sc;
            Qs[(d0 + 3) * 64 + r] = v.w * sc;
        }
    }

    float m_i[4], l_i[4], o[4][8];
#pragma unroll
    for (int ii = 0; ii < 4; ii++) {
        m_i[ii] = -1e30f;
        l_i[ii] = 0.0f;
#pragma unroll
        for (int j = 0; j < 8; j++) o[ii][j] = 0.0f;
    }

    for (int kt = 0; kt < SEQ / 64; kt++) {
        __syncthreads();   // previous iteration done reading Ks/Vs/Ps
        // load K tile (transposed) and V tile
        {
            const int r = tid >> 2;
            const int dgb = (tid & 3) * 4;
            const float* ksrc = Kg + (rowbase + (size_t)kt * 64 + r) * HID + coff;
            const float* vsrc = Vg + (rowbase + (size_t)kt * 64 + r) * HID + coff;
#pragma unroll
            for (int dd = 0; dd < 8; dd++) {
                const int d0 = dgb + dd * 16;
                float4 kv = *(const float4*)(ksrc + d0);
                Ks[(d0 + 0) * 64 + r] = kv.x;
                Ks[(d0 + 1) * 64 + r] = kv.y;
                Ks[(d0 + 2) * 64 + r] = kv.z;
                Ks[(d0 + 3) * 64 + r] = kv.w;
                *(float4*)&Vs[r * HD + d0] = *(const float4*)(vsrc + d0);
            }
        }
        __syncthreads();

        // S = (Q*scale) @ K^T  -- 4x4 per thread
        float sacc[4][4];
#pragma unroll
        for (int i = 0; i < 4; i++)
#pragma unroll
            for (int j = 0; j < 4; j++) sacc[i][j] = 0.0f;
#pragma unroll 8
        for (int d = 0; d < HD; d++) {
            float4 qa = *(const float4*)&Qs[d * 64 + ty * 4];
            float4 kb = *(const float4*)&Ks[d * 64 + tx * 4];
            float a[4] = {qa.x, qa.y, qa.z, qa.w};
            float c[4] = {kb.x, kb.y, kb.z, kb.w};
#pragma unroll
            for (int i = 0; i < 4; i++)
#pragma unroll
                for (int j = 0; j < 4; j++)
                    sacc[i][j] = fmaf(a[i], c[j], sacc[i][j]);
        }

        // online softmax per row (reduce across 16 tx lanes)
#pragma unroll
        for (int ii = 0; ii < 4; ii++) {
            float mx = fmaxf(fmaxf(sacc[ii][0], sacc[ii][1]),
                             fmaxf(sacc[ii][2], sacc[ii][3]));
#pragma unroll
            for (int off = 8; off >= 1; off >>= 1)
                mx = fmaxf(mx, __shfl_xor_sync(0xffffffffu, mx, off));
            const float mnew = fmaxf(m_i[ii], mx);
            const float corr = __expf(m_i[ii] - mnew);
            m_i[ii] = mnew;
            float rs = 0.0f;
#pragma unroll
            for (int j = 0; j < 4; j++) {
                float p = __expf(sacc[ii][j] - mnew);
                sacc[ii][j] = p;
                rs += p;
            }
#pragma unroll
            for (int off = 8; off >= 1; off >>= 1)
                rs += __shfl_xor_sync(0xffffffffu, rs, off);
            l_i[ii] = l_i[ii] * corr + rs;
#pragma unroll
            for (int j = 0; j < 8; j++) o[ii][j] *= corr;
            const int prow = (ty * 4 + ii) * 65;
#pragma unroll
            for (int j = 0; j < 4; j++) Ps[prow + tx * 4 + j] = sacc[ii][j];
        }
        __syncthreads();

        // O += P @ V
#pragma unroll 4
        for (int kk = 0; kk < 64; kk++) {
            float4 v0 = *(const float4*)&Vs[kk * HD + tx * 4];
            float4 v1 = *(const float4*)&Vs[kk * HD + 64 + tx * 4];
#pragma unroll
            for (int ii = 0; ii < 4; ii++) {
                const float p = Ps[(ty * 4 + ii) * 65 + kk];
                o[ii][0] = fmaf(p, v0.x, o[ii][0]);
                o[ii][1] = fmaf(p, v0.y, o[ii][1]);
                o[ii][2] = fmaf(p, v0.z, o[ii][2]);
                o[ii][3] = fmaf(p, v0.w, o[ii][3]);
                o[ii][4] = fmaf(p, v1.x, o[ii][4]);
                o[ii][5] = fmaf(p, v1.y, o[ii][5]);
                o[ii][6] = fmaf(p, v1.z, o[ii][6]);
                o[ii][7] = fmaf(p, v1.w, o[ii][7]);
            }
        }
    }

    // normalize & write context in [B*S, H] row-major
#pragma unroll
    for (int ii = 0; ii < 4; ii++) {
        const float inv = 1.0f / l_i[ii];
        float* dst = Og + (rowbase + q0 + ty * 4 + ii) * HID + coff;
        float4 r0, r1;
        r0.x = o[ii][0] * inv; r0.y = o[ii][1] * inv;
        r0.z = o[ii][2] * inv; r0.w = o[ii][3] * inv;
        r1.x = o[ii][4] * inv; r1.y = o[ii][5] * inv;
        r1.z = o[ii][6] * inv; r1.w = o[ii][7] * inv;
        *(float4*)(dst + tx * 4) = r0;
        *(float4*)(dst + 64 + tx * 4) = r1;
    }
}

// ---------------------------------------------------------------------------
extern "C" void kernel_launch(void* const* d_in, const int* in_sizes, int n_in,
                              void* d_out, int out_size)
{
    const float* X  = (const float*)d_in[0];
    const float* Wq = (const float*)d_in[1];
    const float* bq = (const float*)d_in[2];
    const float* Wk = (const float*)d_in[3];
    const float* bk = (const float*)d_in[4];
    const float* Wv = (const float*)d_in[5];
    const float* bv = (const float*)d_in[6];
    const float* Wo = (const float*)d_in[7];
    const float* bo = (const float*)d_in[8];
    float* out = (float*)d_out;

    float *q, *k, *v, *ctx;
    cudaGetSymbolAddress((void**)&q,   g_q);
    cudaGetSymbolAddress((void**)&k,   g_k);
    cudaGetSymbolAddress((void**)&v,   g_v);
    cudaGetSymbolAddress((void**)&ctx, g_ctx);

    cudaFuncSetAttribute(flash_kernel,
                         cudaFuncAttributeMaxDynamicSharedMemorySize,
                         (int)FL_SMEM);

    // 1) QKV projections + bias + RoPE (fused epilogue)
    {
        dim3 grid(HID / 128, M_ROWS / 128, 3);
        gemm_qkv_kernel<<<grid, 256>>>(X, Wq, bq, Wk, bk, Wv, bv, q, k, v);
    }
    // 2) flash attention -> context
    {
        dim3 grid(SEQ / 64, BATCH * NH);
        flash_kernel<<<grid, 256, FL_SMEM>>>(q, k, v, ctx);
    }
    // 3) output projection
    {
        dim3 grid(HID / 128, M_ROWS / 128);
        gemm_out_kernel<<<grid, 256>>>(ctx, Wo, bo, out);
    }
}

// round 3
// speedup vs baseline: 1.5319x; 1.5319x over previous
#include <cuda_runtime.h>
#include <cuda_bf16.h>
#include <cstdint>
#include <math.h>

#define HID 2048
#define SEQ 2048
#define NH  16
#define HD  128
#define BATCH 2
#define M_ROWS (BATCH*SEQ)   // 4096

// ---------------------------------------------------------------------------
// Scratch (__device__ globals; no allocation allowed)
// ---------------------------------------------------------------------------
__device__ __nv_bfloat16 g_xh[(size_t)M_ROWS * HID];
__device__ __nv_bfloat16 g_xl[(size_t)M_ROWS * HID];
__device__ __nv_bfloat16 g_wqh[(size_t)HID * HID];
__device__ __nv_bfloat16 g_wql[(size_t)HID * HID];
__device__ __nv_bfloat16 g_wkh[(size_t)HID * HID];
__device__ __nv_bfloat16 g_wkl[(size_t)HID * HID];
__device__ __nv_bfloat16 g_wvh[(size_t)HID * HID];
__device__ __nv_bfloat16 g_wvl[(size_t)HID * HID];
__device__ __nv_bfloat16 g_woh[(size_t)HID * HID];
__device__ __nv_bfloat16 g_wol[(size_t)HID * HID];
__device__ float g_q[(size_t)M_ROWS * HID];
__device__ float g_k[(size_t)M_ROWS * HID];
__device__ float g_v[(size_t)M_ROWS * HID];
__device__ __nv_bfloat16 g_cxh[(size_t)M_ROWS * HID];
__device__ __nv_bfloat16 g_cxl[(size_t)M_ROWS * HID];
__device__ float g_sin[SEQ * (HD/2)];
__device__ float g_cos[SEQ * (HD/2)];

// ---------------------------------------------------------------------------
// helpers
// ---------------------------------------------------------------------------
__device__ __forceinline__ uint32_t smem_to_u32(const void* p) {
    uint32_t a;
    asm("{ .reg .u64 t; cvta.to.shared.u64 t, %1; cvt.u32.u64 %0, t; }"
        : "=r"(a) : "l"(p));
    return a;
}

__device__ __forceinline__ void cp16(uint32_t dst, const void* src) {
    asm volatile("cp.async.cg.shared.global [%0], [%1], 16;"
                 :: "r"(dst), "l"(src) : "memory");
}

__device__ __forceinline__ void ldsm_x4(uint32_t* r, uint32_t addr) {
    asm volatile("ldmatrix.sync.aligned.m8n8.x4.shared.b16 {%0,%1,%2,%3}, [%4];"
                 : "=r"(r[0]), "=r"(r[1]), "=r"(r[2]), "=r"(r[3]) : "r"(addr));
}

__device__ __forceinline__ void mma_bf16(float* c, const uint32_t* a,
                                         uint32_t b0, uint32_t b1) {
    asm volatile(
        "mma.sync.aligned.m16n8k16.row.col.f32.bf16.bf16.f32 "
        "{%0,%1,%2,%3}, {%4,%5,%6,%7}, {%8,%9}, {%0,%1,%2,%3};"
        : "+f"(c[0]), "+f"(c[1]), "+f"(c[2]), "+f"(c[3])
        : "r"(a[0]), "r"(a[1]), "r"(a[2]), "r"(a[3]), "r"(b0), "r"(b1));
}

__device__ __forceinline__ void splitf(float v, __nv_bfloat16& h, __nv_bfloat16& l) {
    h = __float2bfloat16_rn(v);
    l = __float2bfloat16_rn(v - __bfloat162float(h));
}
__device__ __forceinline__ uint32_t pk2(__nv_bfloat16 a, __nv_bfloat16 b) {
    __nv_bfloat162 t = __halves2bfloat162(a, b);
    return *reinterpret_cast<uint32_t*>(&t);
}

// ---------------------------------------------------------------------------
// Prep kernels
// ---------------------------------------------------------------------------
__global__ void rope_table_kernel(float* __restrict__ st, float* __restrict__ ct) {
    int idx = blockIdx.x * blockDim.x + threadIdx.x;   // SEQ*64
    int s = idx >> 6, j = idx & 63;
    double f = exp(-0.14391156831212787 * (double)j);  // 10000^(-2j/128)
    double sn, cs;
    sincos((double)s * f, &sn, &cs);
    st[idx] = (float)sn;
    ct[idx] = (float)cs;
}

__global__ void __launch_bounds__(256) split_x_kernel(
    const float4* __restrict__ X, uint2* __restrict__ H, uint2* __restrict__ L)
{
    size_t i = (size_t)blockIdx.x * blockDim.x + threadIdx.x;
    float4 v = X[i];
    __nv_bfloat16 h0, l0, h1, l1, h2, l2, h3, l3;
    splitf(v.x, h0, l0); splitf(v.y, h1, l1);
    splitf(v.z, h2, l2); splitf(v.w, h3, l3);
    H[i] = make_uint2(pk2(h0, h1), pk2(h2, h3));
    L[i] = make_uint2(pk2(l0, l1), pk2(l2, l3));
}

// W [K][N] fp32 -> Wt [N][K] bf16 hi/lo (transpose + split)
__global__ void __launch_bounds__(256) wtrans_kernel(
    const float* __restrict__ W, __nv_bfloat16* __restrict__ Th,
    __nv_bfloat16* __restrict__ Tl)
{
    __shared__ float t[32][33];
    const int n0 = blockIdx.x * 32, k0 = blockIdx.y * 32;
    const int tx = threadIdx.x, ty = threadIdx.y;   // (32, 8)
#pragma unroll
    for (int i = 0; i < 4; i++)
        t[ty + 8 * i][tx] = W[(size_t)(k0 + ty + 8 * i) * HID + n0 + tx];
    __syncthreads();
#pragma unroll
    for (int i = 0; i < 4; i++) {
        float v = t[tx][ty + 8 * i];
        __nv_bfloat16 h, l;
        splitf(v, h, l);
        const size_t o = (size_t)(n0 + ty + 8 * i) * HID + k0 + tx;
        Th[o] = h;
        Tl[o] = l;
    }
}

// ---------------------------------------------------------------------------
// mma.sync split-bf16 GEMM.  Y[4096][2048] = A(bf16 hi/lo) * Wt^T (+bias,+RoPE)
// BM=BN=128, BK=32, 8 warps (warp tile 32x64), 4-stage cp.async pipeline.
// Virtual K = 3 product segments: Ah*Bh, Al*Bh, Ah*Bl.
// ---------------------------------------------------------------------------
#define BKC 32
#define ROWP 40                         // padded row length (bf16 elems)
#define TILE_BYTES (128 * ROWP * 2)     // 10240
#define STAGE_BYTES (2 * TILE_BYTES)    // A tile + B tile
#define STAGES 4
#define GSMEM (STAGES * STAGE_BYTES)    // 81920
#define NVCHUNK (3 * HID / BKC)         // 192

__device__ __forceinline__ void gemm_mma_body(
    const __nv_bfloat16* __restrict__ Ah, const __nv_bfloat16* __restrict__ Al,
    const __nv_bfloat16* __restrict__ Bh, const __nv_bfloat16* __restrict__ Bl,
    const float* __restrict__ bias, float* __restrict__ Y,
    const float* __restrict__ stab, const float* __restrict__ ctab, int rope)
{
    extern __shared__ __align__(128) char smem[];
    const uint32_t sb = smem_to_u32(smem);
    const int tid = threadIdx.x;
    const int wid = tid >> 5, lane = tid & 31;
    const int warp_m = wid & 3, warp_n = wid >> 2;
    const int bm = blockIdx.y * 128, bn = blockIdx.x * 128;

    // cp.async destinations (each thread: 2 rows in A tile, 2 in B tile)
    const int lrow = tid >> 2, lch = tid & 3;
    const uint32_t dA = sb + lrow * 80 + lch * 16;
    const uint32_t dB = sb + TILE_BYTES + lrow * 80 + lch * 16;
    const int gcol = lch * 8;

    // ldmatrix base offsets
    const uint32_t aoff =
        ((warp_m * 32 + ((lane >> 3) & 1) * 8 + (lane & 7)) * ROWP +
         (lane >> 4) * 8) * 2;
    const uint32_t boff =
        ((warp_n * 64 + ((lane >> 4) & 1) * 8 + (lane & 7)) * ROWP +
         ((lane >> 3) & 1) * 8) * 2;
    const uint32_t aBase = sb + aoff;
    const uint32_t bBase = sb + TILE_BYTES + boff;

    float acc[2][8][4];
#pragma unroll
    for (int mt = 0; mt < 2; mt++)
#pragma unroll
        for (int nt = 0; nt < 8; nt++)
#pragma unroll
            for (int e = 0; e < 4; e++) acc[mt][nt][e] = 0.0f;

    auto issue = [&](int cv, int stage) {
        const int prod = cv >> 6;
        const int k0 = (cv & 63) << 5;
        const __nv_bfloat16* As = (prod == 1) ? Al : Ah;
        const __nv_bfloat16* Bs = (prod == 2) ? Bl : Bh;
        const __nv_bfloat16* ap = As + (size_t)(bm + lrow) * HID + k0 + gcol;
        const __nv_bfloat16* bp = Bs + (size_t)(bn + lrow) * HID + k0 + gcol;
        const uint32_t so = stage * STAGE_BYTES;
        cp16(dA + so, ap);
        cp16(dA + so + 64 * 80, ap + (size_t)64 * HID);
        cp16(dB + so, bp);
        cp16(dB + so + 64 * 80, bp + (size_t)64 * HID);
    };

#pragma unroll
    for (int s = 0; s < STAGES; s++) {
        issue(s, s);
        asm volatile("cp.async.commit_group;" ::: "memory");
    }

    for (int cv = 0; cv < NVCHUNK; cv++) {
        asm volatile("cp.async.wait_group 3;" ::: "memory");
        __syncthreads();
        const uint32_t so = (cv & 3) * STAGE_BYTES;
#pragma unroll
        for (int ks = 0; ks < 2; ks++) {
            uint32_t a[2][4], b[4][4];
#pragma unroll
            for (int mt = 0; mt < 2; mt++)
                ldsm_x4(a[mt], aBase + so + mt * (16 * ROWP * 2) + ks * 32);
#pragma unroll
            for (int nb = 0; nb < 4; nb++)
                ldsm_x4(b[nb], bBase + so + nb * (16 * ROWP * 2) + ks * 32);
#pragma unroll
            for (int mt = 0; mt < 2; mt++)
#pragma unroll
                for (int nt = 0; nt < 8; nt++) {
                    const uint32_t* bb = b[nt >> 1];
                    if (nt & 1) mma_bf16(acc[mt][nt], a[mt], bb[2], bb[3]);
                    else        mma_bf16(acc[mt][nt], a[mt], bb[0], bb[1]);
                }
        }
        __syncthreads();
        if (cv + STAGES < NVCHUNK) issue(cv + STAGES, cv & 3);
        asm volatile("cp.async.commit_group;" ::: "memory");
    }

    // epilogue: bias (+RoPE) and direct stores (float2 per fragment row)
    const int r0 = bm + warp_m * 32 + (lane >> 2);
    const int c0base = bn + warp_n * 64 + (lane & 3) * 2;
#pragma unroll
    for (int mt = 0; mt < 2; mt++) {
#pragma unroll
        for (int half = 0; half < 2; half++) {
            const int row = r0 + mt * 16 + half * 8;
            const int s = row & (SEQ - 1);
            float* yrow = Y + (size_t)row * HID;
#pragma unroll
            for (int nt = 0; nt < 8; nt++) {
                const int col = c0base + nt * 8;
                float e  = acc[mt][nt][half * 2 + 0] + bias[col];
                float od = acc[mt][nt][half * 2 + 1] + bias[col + 1];
                float2 r;
                if (rope) {
                    const int j = (col & (HD - 1)) >> 1;
                    const float sn = stab[(s << 6) + j];
                    const float cs = ctab[(s << 6) + j];
                    r.x = e * cs - od * sn;
                    r.y = od * cs + e * sn;
                } else {
                    r.x = e;
                    r.y = od;
                }
                *(float2*)(yrow + col) = r;
            }
        }
    }
}

__global__ void __launch_bounds__(256, 2) mma_gemm_qkv_kernel(
    const __nv_bfloat16* xh, const __nv_bfloat16* xl,
    const __nv_bfloat16* wqh, const __nv_bfloat16* wql,
    const __nv_bfloat16* wkh, const __nv_bfloat16* wkl,
    const __nv_bfloat16* wvh, const __nv_bfloat16* wvl,
    const float* bq, const float* bk, const float* bv,
    float* q, float* k, float* v,
    const float* stab, const float* ctab)
{
    const __nv_bfloat16 *Bh, *Bl;
    const float* bias;
    float* Y;
    int rope;
    if (blockIdx.z == 0)      { Bh = wqh; Bl = wql; bias = bq; Y = q; rope = 1; }
    else if (blockIdx.z == 1) { Bh = wkh; Bl = wkl; bias = bk; Y = k; rope = 1; }
    else                      { Bh = wvh; Bl = wvl; bias = bv; Y = v; rope = 0; }
    gemm_mma_body(xh, xl, Bh, Bl, bias, Y, stab, ctab, rope);
}

__global__ void __launch_bounds__(256, 2) mma_gemm_out_kernel(
    const __nv_bfloat16* ah, const __nv_bfloat16* al,
    const __nv_bfloat16* wh, const __nv_bfloat16* wl,
    const float* bo, float* Y)
{
    gemm_mma_body(ah, al, wh, wl, bo, Y, nullptr, nullptr, 0);
}

// ---------------------------------------------------------------------------
// Flash attention, fp32. Br=Bc=64, HD=128. 256 threads (16x16).
// Writes context as split bf16 hi/lo for the output projection.
// ---------------------------------------------------------------------------
#define FL_SMEM ((HD*64 + HD*64 + 64*HD + 64*65) * sizeof(float))

__global__ void __launch_bounds__(256) flash_kernel(
    const float* __restrict__ Qg, const float* __restrict__ Kg,
    const float* __restrict__ Vg,
    __nv_bfloat16* __restrict__ CtxH, __nv_bfloat16* __restrict__ CtxL)
{
    extern __shared__ float sm[];
    float* Qs = sm;              // [HD][64]
    float* Ks = Qs + HD * 64;    // [HD][64]
    float* Vs = Ks + HD * 64;    // [64][HD]
    float* Ps = Vs + 64 * HD;    // [64][65]

    const int tid = threadIdx.x;
    const int tx = tid & 15, ty = tid >> 4;
    const int bh = blockIdx.y;
    const int b = bh / NH, h = bh % NH;
    const int q0 = blockIdx.x * 64;
    const size_t rowbase = (size_t)b * SEQ;
    const int coff = h * HD;

    {
        const int r = tid >> 2;
        const int dgb = (tid & 3) * 4;
        const float* src = Qg + (rowbase + q0 + r) * HID + coff;
        const float sc = 0.08838834764831845f;   // 1/sqrt(128)
#pragma unroll
        for (int dd = 0; dd < 8; dd++) {
            const int d0 = dgb + dd * 16;
            float4 v = *(const float4*)(src + d0);
            Qs[(d0 + 0) * 64 + r] = v.x * sc;
            Qs[(d0 + 1) * 64 + r] = v.y * sc;
            Qs[(d0 + 2) * 64 + r] = v.z * sc;
            Qs[(d0 + 3) * 64 + r] = v.w * sc;
        }
    }

    float m_i[4], l_i[4], o[4][8];
#pragma unroll
    for (int ii = 0; ii < 4; ii++) {
        m_i[ii] = -1e30f;
        l_i[ii] = 0.0f;
#pragma unroll
        for (int j = 0; j < 8; j++) o[ii][j] = 0.0f;
    }

    for (int kt = 0; kt < SEQ / 64; kt++) {
        __syncthreads();
        {
            const int r = tid >> 2;
            const int dgb = (tid & 3) * 4;
            const float* ksrc = Kg + (rowbase + (size_t)kt * 64 + r) * HID + coff;
            const float* vsrc = Vg + (rowbase + (size_t)kt * 64 + r) * HID + coff;
#pragma unroll
            for (int dd = 0; dd < 8; dd++) {
                const int d0 = dgb + dd * 16;
                float4 kv = *(const float4*)(ksrc + d0);
                Ks[(d0 + 0) * 64 + r] = kv.x;
                Ks[(d0 + 1) * 64 + r] = kv.y;
                Ks[(d0 + 2) * 64 + r] = kv.z;
                Ks[(d0 + 3) * 64 + r] = kv.w;
                *(float4*)&Vs[r * HD + d0] = *(const float4*)(vsrc + d0);
            }
        }
        __syncthreads();

        float sacc[4][4];
#pragma unroll
        for (int i = 0; i < 4; i++)
#pragma unroll
            for (int j = 0; j < 4; j++) sacc[i][j] = 0.0f;
#pragma unroll 8
        for (int d = 0; d < HD; d++) {
            float4 qa = *(const float4*)&Qs[d * 64 + ty * 4];
            float4 kb = *(const float4*)&Ks[d * 64 + tx * 4];
            float a[4] = {qa.x, qa.y, qa.z, qa.w};
            float cc[4] = {kb.x, kb.y, kb.z, kb.w};
#pragma unroll
            for (int i = 0; i < 4; i++)
#pragma unroll
                for (int j = 0; j < 4; j++)
                    sacc[i][j] = fmaf(a[i], cc[j], sacc[i][j]);
        }

#pragma unroll
        for (int ii = 0; ii < 4; ii++) {
            float mx = fmaxf(fmaxf(sacc[ii][0], sacc[ii][1]),
                             fmaxf(sacc[ii][2], sacc[ii][3]));
#pragma unroll
            for (int off = 8; off >= 1; off >>= 1)
                mx = fmaxf(mx, __shfl_xor_sync(0xffffffffu, mx, off));
            const float mnew = fmaxf(m_i[ii], mx);
            const float corr = __expf(m_i[ii] - mnew);
            m_i[ii] = mnew;
            float rs = 0.0f;
#pragma unroll
            for (int j = 0; j < 4; j++) {
                float p = __expf(sacc[ii][j] - mnew);
                sacc[ii][j] = p;
                rs += p;
            }
#pragma unroll
            for (int off = 8; off >= 1; off >>= 1)
                rs += __shfl_xor_sync(0xffffffffu, rs, off);
            l_i[ii] = l_i[ii] * corr + rs;
#pragma unroll
            for (int j = 0; j < 8; j++) o[ii][j] *= corr;
            const int prow = (ty * 4 + ii) * 65;
#pragma unroll
            for (int j = 0; j < 4; j++) Ps[prow + tx * 4 + j] = sacc[ii][j];
        }
        __syncthreads();

#pragma unroll 4
        for (int kk = 0; kk < 64; kk++) {
            float4 v0 = *(const float4*)&Vs[kk * HD + tx * 4];
            float4 v1 = *(const float4*)&Vs[kk * HD + 64 + tx * 4];
#pragma unroll
            for (int ii = 0; ii < 4; ii++) {
                const float p = Ps[(ty * 4 + ii) * 65 + kk];
                o[ii][0] = fmaf(p, v0.x, o[ii][0]);
                o[ii][1] = fmaf(p, v0.y, o[ii][1]);
                o[ii][2] = fmaf(p, v0.z, o[ii][2]);
                o[ii][3] = fmaf(p, v0.w, o[ii][3]);
                o[ii][4] = fmaf(p, v1.x, o[ii][4]);
                o[ii][5] = fmaf(p, v1.y, o[ii][5]);
                o[ii][6] = fmaf(p, v1.z, o[ii][6]);
                o[ii][7] = fmaf(p, v1.w, o[ii][7]);
            }
        }
    }

#pragma unroll
    for (int ii = 0; ii < 4; ii++) {
        const float inv = 1.0f / l_i[ii];
        const size_t row = rowbase + q0 + ty * 4 + ii;
        __nv_bfloat16* dh = CtxH + row * HID + coff;
        __nv_bfloat16* dl = CtxL + row * HID + coff;
#pragma unroll
        for (int half = 0; half < 2; half++) {
            float v0 = o[ii][half * 4 + 0] * inv;
            float v1 = o[ii][half * 4 + 1] * inv;
            float v2 = o[ii][half * 4 + 2] * inv;
            float v3 = o[ii][half * 4 + 3] * inv;
            __nv_bfloat16 h0, l0, h1, l1, h2, l2, h3, l3;
            splitf(v0, h0, l0); splitf(v1, h1, l1);
            splitf(v2, h2, l2); splitf(v3, h3, l3);
            uint2 hv = make_uint2(pk2(h0, h1), pk2(h2, h3));
            uint2 lv = make_uint2(pk2(l0, l1), pk2(l2, l3));
            *(uint2*)(dh + half * 64 + tx * 4) = hv;
            *(uint2*)(dl + half * 64 + tx * 4) = lv;
        }
    }
}

// ---------------------------------------------------------------------------
extern "C" void kernel_launch(void* const* d_in, const int* in_sizes, int n_in,
                              void* d_out, int out_size)
{
    const float* X  = (const float*)d_in[0];
    const float* Wq = (const float*)d_in[1];
    const float* bq = (const float*)d_in[2];
    const float* Wk = (const float*)d_in[3];
    const float* bk = (const float*)d_in[4];
    const float* Wv = (const float*)d_in[5];
    const float* bv = (const float*)d_in[6];
    const float* Wo = (const float*)d_in[7];
    const float* bo = (const float*)d_in[8];
    float* out = (float*)d_out;

    __nv_bfloat16 *xh, *xl, *wqh, *wql, *wkh, *wkl, *wvh, *wvl, *woh, *wol;
    __nv_bfloat16 *cxh, *cxl;
    float *q, *k, *v, *stab, *ctab;
    cudaGetSymbolAddress((void**)&xh,  g_xh);
    cudaGetSymbolAddress((void**)&xl,  g_xl);
    cudaGetSymbolAddress((void**)&wqh, g_wqh);
    cudaGetSymbolAddress((void**)&wql, g_wql);
    cudaGetSymbolAddress((void**)&wkh, g_wkh);
    cudaGetSymbolAddress((void**)&wkl, g_wkl);
    cudaGetSymbolAddress((void**)&wvh, g_wvh);
    cudaGetSymbolAddress((void**)&wvl, g_wvl);
    cudaGetSymbolAddress((void**)&woh, g_woh);
    cudaGetSymbolAddress((void**)&wol, g_wol);
    cudaGetSymbolAddress((void**)&cxh, g_cxh);
    cudaGetSymbolAddress((void**)&cxl, g_cxl);
    cudaGetSymbolAddress((void**)&q,   g_q);
    cudaGetSymbolAddress((void**)&k,   g_k);
    cudaGetSymbolAddress((void**)&v,   g_v);
    cudaGetSymbolAddress((void**)&stab, g_sin);
    cudaGetSymbolAddress((void**)&ctab, g_cos);

    cudaFuncSetAttribute(mma_gemm_qkv_kernel,
                         cudaFuncAttributeMaxDynamicSharedMemorySize, GSMEM);
    cudaFuncSetAttribute(mma_gemm_out_kernel,
                         cudaFuncAttributeMaxDynamicSharedMemorySize, GSMEM);
    cudaFuncSetAttribute(flash_kernel,
                         cudaFuncAttributeMaxDynamicSharedMemorySize, (int)FL_SMEM);

    // 0) RoPE sin/cos table (double precision)
    rope_table_kernel<<<SEQ * 64 / 256, 256>>>(stab, ctab);

    // 1) split X into bf16 hi/lo
    split_x_kernel<<<(int)(((size_t)M_ROWS * HID / 4) / 256), 256>>>(
        (const float4*)X, (uint2*)xh, (uint2*)xl);

    // 2) transpose + split weights
    {
        dim3 g(HID / 32, HID / 32), blk(32, 8);
        wtrans_kernel<<<g, blk>>>(Wq, wqh, wql);
        wtrans_kernel<<<g, blk>>>(Wk, wkh, wkl);
        wtrans_kernel<<<g, blk>>>(Wv, wvh, wvl);
        wtrans_kernel<<<g, blk>>>(Wo, woh, wol);
    }

    // 3) QKV projections (mma.sync) + bias + RoPE
    {
        dim3 grid(HID / 128, M_ROWS / 128, 3);
        mma_gemm_qkv_kernel<<<grid, 256, GSMEM>>>(
            xh, xl, wqh, wql, wkh, wkl, wvh, wvl, bq, bk, bv, q, k, v, stab, ctab);
    }

    // 4) flash attention -> split-bf16 context
    {
        dim3 grid(SEQ / 64, BATCH * NH);
        flash_kernel<<<grid, 256, FL_SMEM>>>(q, k, v, cxh, cxl);
    }

    // 5) output projection (mma.sync) + bias -> out
    {
        dim3 grid(HID / 128, M_ROWS / 128);
        mma_gemm_out_kernel<<<grid, 256, GSMEM>>>(cxh, cxl, woh, wol, bo, out);
    }
}

// round 4
// speedup vs baseline: 2.4336x; 1.5887x over previous
#include <cuda_runtime.h>
#include <cuda_bf16.h>
#include <cstdint>
#include <math.h>

#define HID 2048
#define SEQ 2048
#define NH  16
#define HD  128
#define BATCH 2
#define M_ROWS (BATCH*SEQ)   // 4096

// ---------------------------------------------------------------------------
// Scratch (__device__ globals; no allocation allowed)
// ---------------------------------------------------------------------------
__device__ __nv_bfloat16 g_xh[(size_t)M_ROWS * HID];
__device__ __nv_bfloat16 g_xl[(size_t)M_ROWS * HID];
__device__ __nv_bfloat16 g_wqh[(size_t)HID * HID];
__device__ __nv_bfloat16 g_wql[(size_t)HID * HID];
__device__ __nv_bfloat16 g_wkh[(size_t)HID * HID];
__device__ __nv_bfloat16 g_wkl[(size_t)HID * HID];
__device__ __nv_bfloat16 g_wvh[(size_t)HID * HID];
__device__ __nv_bfloat16 g_wvl[(size_t)HID * HID];
__device__ __nv_bfloat16 g_woh[(size_t)HID * HID];
__device__ __nv_bfloat16 g_wol[(size_t)HID * HID];
__device__ __nv_bfloat16 g_qh[(size_t)M_ROWS * HID];
__device__ __nv_bfloat16 g_ql[(size_t)M_ROWS * HID];
__device__ __nv_bfloat16 g_kh[(size_t)M_ROWS * HID];
__device__ __nv_bfloat16 g_kl[(size_t)M_ROWS * HID];
__device__ __nv_bfloat16 g_vh[(size_t)M_ROWS * HID];
__device__ __nv_bfloat16 g_vl[(size_t)M_ROWS * HID];
__device__ __nv_bfloat16 g_cxh[(size_t)M_ROWS * HID];
__device__ __nv_bfloat16 g_cxl[(size_t)M_ROWS * HID];
__device__ float g_sin[SEQ * (HD/2)];
__device__ float g_cos[SEQ * (HD/2)];

// ---------------------------------------------------------------------------
// helpers
// ---------------------------------------------------------------------------
__device__ __forceinline__ uint32_t smem_to_u32(const void* p) {
    uint32_t a;
    asm("{ .reg .u64 t; cvta.to.shared.u64 t, %1; cvt.u32.u64 %0, t; }"
        : "=r"(a) : "l"(p));
    return a;
}

__device__ __forceinline__ void cp16(uint32_t dst, const void* src) {
    asm volatile("cp.async.cg.shared.global [%0], [%1], 16;"
                 :: "r"(dst), "l"(src) : "memory");
}

__device__ __forceinline__ void ldsm_x4(uint32_t* r, uint32_t addr) {
    asm volatile("ldmatrix.sync.aligned.m8n8.x4.shared.b16 {%0,%1,%2,%3}, [%4];"
                 : "=r"(r[0]), "=r"(r[1]), "=r"(r[2]), "=r"(r[3]) : "r"(addr));
}

__device__ __forceinline__ void ldsm_x4_t(uint32_t* r, uint32_t addr) {
    asm volatile("ldmatrix.sync.aligned.m8n8.x4.trans.shared.b16 {%0,%1,%2,%3}, [%4];"
                 : "=r"(r[0]), "=r"(r[1]), "=r"(r[2]), "=r"(r[3]) : "r"(addr));
}

__device__ __forceinline__ void mma_bf16(float* c, const uint32_t* a,
                                         uint32_t b0, uint32_t b1) {
    asm volatile(
        "mma.sync.aligned.m16n8k16.row.col.f32.bf16.bf16.f32 "
        "{%0,%1,%2,%3}, {%4,%5,%6,%7}, {%8,%9}, {%0,%1,%2,%3};"
        : "+f"(c[0]), "+f"(c[1]), "+f"(c[2]), "+f"(c[3])
        : "r"(a[0]), "r"(a[1]), "r"(a[2]), "r"(a[3]), "r"(b0), "r"(b1));
}

__device__ __forceinline__ void splitf(float v, __nv_bfloat16& h, __nv_bfloat16& l) {
    h = __float2bfloat16_rn(v);
    l = __float2bfloat16_rn(v - __bfloat162float(h));
}
__device__ __forceinline__ uint32_t pk2(__nv_bfloat16 a, __nv_bfloat16 b) {
    __nv_bfloat162 t = __halves2bfloat162(a, b);
    return *reinterpret_cast<uint32_t*>(&t);
}

// ---------------------------------------------------------------------------
// Prep kernels
// ---------------------------------------------------------------------------
__global__ void rope_table_kernel(float* __restrict__ st, float* __restrict__ ct) {
    int idx = blockIdx.x * blockDim.x + threadIdx.x;   // SEQ*64
    int s = idx >> 6, j = idx & 63;
    double f = exp(-0.14391156831212787 * (double)j);  // 10000^(-2j/128)
    double sn, cs;
    sincos((double)s * f, &sn, &cs);
    st[idx] = (float)sn;
    ct[idx] = (float)cs;
}

__global__ void __launch_bounds__(256) split_x_kernel(
    const float4* __restrict__ X, uint2* __restrict__ H, uint2* __restrict__ L)
{
    size_t i = (size_t)blockIdx.x * blockDim.x + threadIdx.x;
    float4 v = X[i];
    __nv_bfloat16 h0, l0, h1, l1, h2, l2, h3, l3;
    splitf(v.x, h0, l0); splitf(v.y, h1, l1);
    splitf(v.z, h2, l2); splitf(v.w, h3, l3);
    H[i] = make_uint2(pk2(h0, h1), pk2(h2, h3));
    L[i] = make_uint2(pk2(l0, l1), pk2(l2, l3));
}

// W [K][N] fp32 -> Wt [N][K] bf16 hi/lo (transpose + split)
__global__ void __launch_bounds__(256) wtrans_kernel(
    const float* __restrict__ W, __nv_bfloat16* __restrict__ Th,
    __nv_bfloat16* __restrict__ Tl)
{
    __shared__ float t[32][33];
    const int n0 = blockIdx.x * 32, k0 = blockIdx.y * 32;
    const int tx = threadIdx.x, ty = threadIdx.y;   // (32, 8)
#pragma unroll
    for (int i = 0; i < 4; i++)
        t[ty + 8 * i][tx] = W[(size_t)(k0 + ty + 8 * i) * HID + n0 + tx];
    __syncthreads();
#pragma unroll
    for (int i = 0; i < 4; i++) {
        float v = t[tx][ty + 8 * i];
        __nv_bfloat16 h, l;
        splitf(v, h, l);
        const size_t o = (size_t)(n0 + ty + 8 * i) * HID + k0 + tx;
        Th[o] = h;
        Tl[o] = l;
    }
}

// ---------------------------------------------------------------------------
// mma.sync split-bf16 GEMM.  BM=BN=128, BK=32, 8 warps, 4-stage cp.async.
// mode 0: fp32 out (+bias); mode 1: bias+RoPE, scaled, split-bf16 out;
// mode 2: bias only, split-bf16 out.
// ---------------------------------------------------------------------------
#define ROWP 40                         // padded row length (bf16 elems)
#define TILE_BYTES (128 * ROWP * 2)     // 10240
#define STAGE_BYTES (2 * TILE_BYTES)
#define STAGES 4
#define GSMEM (STAGES * STAGE_BYTES)    // 81920
#define NVCHUNK (3 * HID / 32)          // 192

__device__ __forceinline__ void gemm_mma_body(
    const __nv_bfloat16* __restrict__ Ah, const __nv_bfloat16* __restrict__ Al,
    const __nv_bfloat16* __restrict__ Bh, const __nv_bfloat16* __restrict__ Bl,
    const float* __restrict__ bias,
    float* __restrict__ Yf, __nv_bfloat16* __restrict__ Yh,
    __nv_bfloat16* __restrict__ Yl, float oscale,
    const float* __restrict__ stab, const float* __restrict__ ctab, int mode)
{
    extern __shared__ __align__(128) char smem[];
    const uint32_t sb = smem_to_u32(smem);
    const int tid = threadIdx.x;
    const int wid = tid >> 5, lane = tid & 31;
    const int warp_m = wid & 3, warp_n = wid >> 2;
    const int bm = blockIdx.y * 128, bn = blockIdx.x * 128;

    const int lrow = tid >> 2, lch = tid & 3;
    const uint32_t dA = sb + lrow * 80 + lch * 16;
    const uint32_t dB = sb + TILE_BYTES + lrow * 80 + lch * 16;
    const int gcol = lch * 8;

    const uint32_t aoff =
        ((warp_m * 32 + ((lane >> 3) & 1) * 8 + (lane & 7)) * ROWP +
         (lane >> 4) * 8) * 2;
    const uint32_t boff =
        ((warp_n * 64 + ((lane >> 4) & 1) * 8 + (lane & 7)) * ROWP +
         ((lane >> 3) & 1) * 8) * 2;
    const uint32_t aBase = sb + aoff;
    const uint32_t bBase = sb + TILE_BYTES + boff;

    float acc[2][8][4];
#pragma unroll
    for (int mt = 0; mt < 2; mt++)
#pragma unroll
        for (int nt = 0; nt < 8; nt++)
#pragma unroll
            for (int e = 0; e < 4; e++) acc[mt][nt][e] = 0.0f;

    auto issue = [&](int cv, int stage) {
        const int prod = cv >> 6;
        const int k0 = (cv & 63) << 5;
        const __nv_bfloat16* As = (prod == 1) ? Al : Ah;
        const __nv_bfloat16* Bs = (prod == 2) ? Bl : Bh;
        const __nv_bfloat16* ap = As + (size_t)(bm + lrow) * HID + k0 + gcol;
        const __nv_bfloat16* bp = Bs + (size_t)(bn + lrow) * HID + k0 + gcol;
        const uint32_t so = stage * STAGE_BYTES;
        cp16(dA + so, ap);
        cp16(dA + so + 64 * 80, ap + (size_t)64 * HID);
        cp16(dB + so, bp);
        cp16(dB + so + 64 * 80, bp + (size_t)64 * HID);
    };

#pragma unroll
    for (int s = 0; s < STAGES; s++) {
        issue(s, s);
        asm volatile("cp.async.commit_group;" ::: "memory");
    }

    for (int cv = 0; cv < NVCHUNK; cv++) {
        asm volatile("cp.async.wait_group 3;" ::: "memory");
        __syncthreads();
        const uint32_t so = (cv & 3) * STAGE_BYTES;
#pragma unroll
        for (int ks = 0; ks < 2; ks++) {
            uint32_t a[2][4], b[4][4];
#pragma unroll
            for (int mt = 0; mt < 2; mt++)
                ldsm_x4(a[mt], aBase + so + mt * (16 * ROWP * 2) + ks * 32);
#pragma unroll
            for (int nb = 0; nb < 4; nb++)
                ldsm_x4(b[nb], bBase + so + nb * (16 * ROWP * 2) + ks * 32);
#pragma unroll
            for (int mt = 0; mt < 2; mt++)
#pragma unroll
                for (int nt = 0; nt < 8; nt++) {
                    const uint32_t* bb = b[nt >> 1];
                    if (nt & 1) mma_bf16(acc[mt][nt], a[mt], bb[2], bb[3]);
                    else        mma_bf16(acc[mt][nt], a[mt], bb[0], bb[1]);
                }
        }
        __syncthreads();
        if (cv + STAGES < NVCHUNK) issue(cv + STAGES, cv & 3);
        asm volatile("cp.async.commit_group;" ::: "memory");
    }

    const int r0 = bm + warp_m * 32 + (lane >> 2);
    const int c0base = bn + warp_n * 64 + (lane & 3) * 2;
#pragma unroll
    for (int mt = 0; mt < 2; mt++) {
#pragma unroll
        for (int half = 0; half < 2; half++) {
            const int row = r0 + mt * 16 + half * 8;
            const int s = row & (SEQ - 1);
#pragma unroll
            for (int nt = 0; nt < 8; nt++) {
                const int col = c0base + nt * 8;
                float e  = acc[mt][nt][half * 2 + 0] + bias[col];
                float od = acc[mt][nt][half * 2 + 1] + bias[col + 1];
                if (mode == 1) {
                    const int j = (col & (HD - 1)) >> 1;
                    const float sn = stab[(s << 6) + j];
                    const float cs = ctab[(s << 6) + j];
                    float re = e * cs - od * sn;
                    float ro = od * cs + e * sn;
                    e = re * oscale;
                    od = ro * oscale;
                }
                if (mode == 0) {
                    float2 r;
                    r.x = e; r.y = od;
                    *(float2*)(Yf + (size_t)row * HID + col) = r;
                } else {
                    __nv_bfloat16 h0, l0, h1, l1;
                    splitf(e, h0, l0);
                    splitf(od, h1, l1);
                    *(uint32_t*)(Yh + (size_t)row * HID + col) = pk2(h0, h1);
                    *(uint32_t*)(Yl + (size_t)row * HID + col) = pk2(l0, l1);
                }
            }
        }
    }
}

__global__ void __launch_bounds__(256, 2) mma_gemm_qkv_kernel(
    const __nv_bfloat16* xh, const __nv_bfloat16* xl,
    const __nv_bfloat16* wqh, const __nv_bfloat16* wql,
    const __nv_bfloat16* wkh, const __nv_bfloat16* wkl,
    const __nv_bfloat16* wvh, const __nv_bfloat16* wvl,
    const float* bq, const float* bk, const float* bv,
    __nv_bfloat16* qh, __nv_bfloat16* ql,
    __nv_bfloat16* kh, __nv_bfloat16* kl,
    __nv_bfloat16* vh, __nv_bfloat16* vl,
    const float* stab, const float* ctab)
{
    if (blockIdx.z == 0)
        gemm_mma_body(xh, xl, wqh, wql, bq, nullptr, qh, ql,
                      0.08838834764831845f, stab, ctab, 1);
    else if (blockIdx.z == 1)
        gemm_mma_body(xh, xl, wkh, wkl, bk, nullptr, kh, kl, 1.0f, stab, ctab, 1);
    else
        gemm_mma_body(xh, xl, wvh, wvl, bv, nullptr, vh, vl, 1.0f, nullptr, nullptr, 2);
}

__global__ void __launch_bounds__(256, 2) mma_gemm_out_kernel(
    const __nv_bfloat16* ah, const __nv_bfloat16* al,
    const __nv_bfloat16* wh, const __nv_bfloat16* wl,
    const float* bo, float* Y)
{
    gemm_mma_body(ah, al, wh, wl, bo, Y, nullptr, nullptr, 1.0f, nullptr, nullptr, 0);
}

// ---------------------------------------------------------------------------
// Flash attention v2: tensor-core split-bf16. Br=128, Bc=64, 8 warps.
// Warp w owns Q rows [16w, 16w+16). S acc fragments repack as P A-fragments.
// ---------------------------------------------------------------------------
#define BR 128
#define BC 64
#define RQ 136                  // padded row (bf16 elems); 272B, 17x16B
#define RB (RQ*2)               // 272 bytes per row
#define QBYTES (BR*RB)          // 34816
#define QTOT (2*QBYTES)         // 69632  (Qh + Ql)
#define KVSTG (4*BC*RB)         // 69632  (Kh,Kl,Vh,Vl)
#define FL2_SMEM (QTOT + 2*KVSTG)   // 208896
#define NKT (SEQ/BC)            // 32

__global__ void __launch_bounds__(256, 1) flash2_kernel(
    const __nv_bfloat16* __restrict__ Qh, const __nv_bfloat16* __restrict__ Ql,
    const __nv_bfloat16* __restrict__ Kh, const __nv_bfloat16* __restrict__ Kl,
    const __nv_bfloat16* __restrict__ Vh, const __nv_bfloat16* __restrict__ Vl,
    __nv_bfloat16* __restrict__ CtxH, __nv_bfloat16* __restrict__ CtxL)
{
    extern __shared__ __align__(128) char smem[];
    const uint32_t sb = smem_to_u32(smem);
    const int tid = threadIdx.x;
    const int wid = tid >> 5, lane = tid & 31;
    const int bh = blockIdx.y;
    const int b = bh >> 4, h = bh & 15;
    const int q0 = blockIdx.x * BR;
    const size_t rowbase = (size_t)b * SEQ;
    const int coff = h * HD;

    // ---- load Q tile (hi/lo) via cp.async ----
    {
        const int row = tid >> 1;
        const int ch0 = (tid & 1) * 8;
        const size_t gq = (rowbase + q0 + row) * HID + coff;
        const __nv_bfloat16* sh = Qh + gq;
        const __nv_bfloat16* sl = Ql + gq;
#pragma unroll
        for (int c = 0; c < 8; c++) {
            const int ch = ch0 + c;
            cp16(sb + row * RB + ch * 16, sh + ch * 8);
            cp16(sb + QBYTES + row * RB + ch * 16, sl + ch * 8);
        }
    }

    auto issue_kv = [&](int kt, int stg) {
        const int row = tid >> 2;
        const int cq = tid & 3;
        const size_t g = (rowbase + (size_t)kt * BC + row) * HID + coff;
        const uint32_t base = sb + QTOT + stg * KVSTG + row * RB;
#pragma unroll
        for (int c = 0; c < 4; c++) {
            const int ch = cq + c * 4;
            cp16(base + ch * 16,                 Kh + g + ch * 8);
            cp16(base + 17408 + ch * 16,         Kl + g + ch * 8);
            cp16(base + 34816 + ch * 16,         Vh + g + ch * 8);
            cp16(base + 52224 + ch * 16,         Vl + g + ch * 8);
        }
    };

    issue_kv(0, 0);
    asm volatile("cp.async.commit_group;" ::: "memory");

    // softmax state: rows r0 = lane>>2, r1 = r0+8 (within warp's 16 rows)
    float m0 = -1e30f, m1 = -1e30f, l0 = 0.0f, l1 = 0.0f;
    float oacc[16][4];
#pragma unroll
    for (int nt = 0; nt < 16; nt++)
#pragma unroll
        for (int e = 0; e < 4; e++) oacc[nt][e] = 0.0f;

    // ldmatrix bases
    const uint32_t qBh = sb + (wid * 16 + (lane & 15)) * RB + ((lane >> 4) * 8) * 2;
    const uint32_t qBl = qBh + QBYTES;
    const uint32_t kRel = (((lane >> 4) & 1) * 8 + (lane & 7)) * RB +
                          (((lane >> 3) & 1) * 8) * 2;
    const uint32_t vRel = (lane & 15) * RB + ((lane >> 4) * 8) * 2;

    for (int kt = 0; kt < NKT; kt++) {
        if (kt + 1 < NKT) {
            issue_kv(kt + 1, (kt + 1) & 1);
            asm volatile("cp.async.commit_group;" ::: "memory");
            asm volatile("cp.async.wait_group 1;" ::: "memory");
        } else {
            asm volatile("cp.async.wait_group 0;" ::: "memory");
        }
        __syncthreads();

        const uint32_t kb = sb + QTOT + (kt & 1) * KVSTG;

        // ---- S = Q K^T (split bf16, 3 products) ----
        float sacc[8][4];
#pragma unroll
        for (int nt = 0; nt < 8; nt++)
#pragma unroll
            for (int e = 0; e < 4; e++) sacc[nt][e] = 0.0f;

#pragma unroll
        for (int ks = 0; ks < 8; ks++) {
            uint32_t qa[4], ql4[4];
            ldsm_x4(qa, qBh + ks * 32);
            ldsm_x4(ql4, qBl + ks * 32);
#pragma unroll
            for (int ng = 0; ng < 4; ng++) {
                uint32_t bh4[4], bl4[4];
                const uint32_t ka = kb + kRel + ng * (16 * RB) + ks * 32;
                ldsm_x4(bh4, ka);
                ldsm_x4(bl4, ka + 17408);
                mma_bf16(sacc[2 * ng],     qa,  bh4[0], bh4[1]);
                mma_bf16(sacc[2 * ng],     ql4, bh4[0], bh4[1]);
                mma_bf16(sacc[2 * ng],     qa,  bl4[0], bl4[1]);
                mma_bf16(sacc[2 * ng + 1], qa,  bh4[2], bh4[3]);
                mma_bf16(sacc[2 * ng + 1], ql4, bh4[2], bh4[3]);
                mma_bf16(sacc[2 * ng + 1], qa,  bl4[2], bl4[3]);
            }
        }

        // ---- online softmax (rows r0/r1; quad reduction over lane&3) ----
        float mx0 = -1e30f, mx1 = -1e30f;
#pragma unroll
        for (int nt = 0; nt < 8; nt++) {
            mx0 = fmaxf(mx0, fmaxf(sacc[nt][0], sacc[nt][1]));
            mx1 = fmaxf(mx1, fmaxf(sacc[nt][2], sacc[nt][3]));
        }
        mx0 = fmaxf(mx0, __shfl_xor_sync(0xffffffffu, mx0, 1));
        mx0 = fmaxf(mx0, __shfl_xor_sync(0xffffffffu, mx0, 2));
        mx1 = fmaxf(mx1, __shfl_xor_sync(0xffffffffu, mx1, 1));
        mx1 = fmaxf(mx1, __shfl_xor_sync(0xffffffffu, mx1, 2));

        const float mn0 = fmaxf(m0, mx0);
        const float mn1 = fmaxf(m1, mx1);
        const float corr0 = __expf(m0 - mn0);
        const float corr1 = __expf(m1 - mn1);
        m0 = mn0;
        m1 = mn1;

        uint32_t ph0[8], ph1[8], pl0[8], pl1[8];
        float rs0 = 0.0f, rs1 = 0.0f;
#pragma unroll
        for (int nt = 0; nt < 8; nt++) {
            float p00 = __expf(sacc[nt][0] - mn0);
            float p01 = __expf(sacc[nt][1] - mn0);
            float p10 = __expf(sacc[nt][2] - mn1);
            float p11 = __expf(sacc[nt][3] - mn1);
            rs0 += p00 + p01;
            rs1 += p10 + p11;
            __nv_bfloat16 a, bb, c, d;
            splitf(p00, a, bb); splitf(p01, c, d);
            ph0[nt] = pk2(a, c); pl0[nt] = pk2(bb, d);
            splitf(p10, a, bb); splitf(p11, c, d);
            ph1[nt] = pk2(a, c); pl1[nt] = pk2(bb, d);
        }
        rs0 += __shfl_xor_sync(0xffffffffu, rs0, 1);
        rs0 += __shfl_xor_sync(0xffffffffu, rs0, 2);
        rs1 += __shfl_xor_sync(0xffffffffu, rs1, 1);
        rs1 += __shfl_xor_sync(0xffffffffu, rs1, 2);
        l0 = l0 * corr0 + rs0;
        l1 = l1 * corr1 + rs1;

#pragma unroll
        for (int nt = 0; nt < 16; nt++) {
            oacc[nt][0] *= corr0;
            oacc[nt][1] *= corr0;
            oacc[nt][2] *= corr1;
            oacc[nt][3] *= corr1;
        }

        // ---- O += P V (split bf16, 3 products; V via ldmatrix.trans) ----
        const uint32_t vb = kb + 34816;
#pragma unroll
        for (int ks2 = 0; ks2 < 4; ks2++) {
            uint32_t ah[4] = {ph0[2 * ks2], ph1[2 * ks2],
                              ph0[2 * ks2 + 1], ph1[2 * ks2 + 1]};
            uint32_t al[4] = {pl0[2 * ks2], pl1[2 * ks2],
                              pl0[2 * ks2 + 1], pl1[2 * ks2 + 1]};
#pragma unroll
            for (int ng = 0; ng < 8; ng++) {
                uint32_t vh4[4], vl4[4];
                const uint32_t va = vb + vRel + ks2 * (16 * RB) + ng * 32;
                ldsm_x4_t(vh4, va);
                ldsm_x4_t(vl4, va + 17408);
                mma_bf16(oacc[2 * ng],     ah, vh4[0], vh4[1]);
                mma_bf16(oacc[2 * ng],     al, vh4[0], vh4[1]);
                mma_bf16(oacc[2 * ng],     ah, vl4[0], vl4[1]);
                mma_bf16(oacc[2 * ng + 1], ah, vh4[2], vh4[3]);
                mma_bf16(oacc[2 * ng + 1], al, vh4[2], vh4[3]);
                mma_bf16(oacc[2 * ng + 1], ah, vl4[2], vl4[3]);
            }
        }
        __syncthreads();
    }

    // ---- normalize & write split-bf16 context ----
    const float inv0 = 1.0f / l0;
    const float inv1 = 1.0f / l1;
    const size_t row0 = rowbase + q0 + wid * 16 + (lane >> 2);
    const size_t row1 = row0 + 8;
    const int cb = coff + (lane & 3) * 2;
#pragma unroll
    for (int nt = 0; nt < 16; nt++) {
        const int col = cb + nt * 8;
        __nv_bfloat16 h0, lo0, h1, lo1;
        splitf(oacc[nt][0] * inv0, h0, lo0);
        splitf(oacc[nt][1] * inv0, h1, lo1);
        *(uint32_t*)(CtxH + row0 * HID + col) = pk2(h0, h1);
        *(uint32_t*)(CtxL + row0 * HID + col) = pk2(lo0, lo1);
        splitf(oacc[nt][2] * inv1, h0, lo0);
        splitf(oacc[nt][3] * inv1, h1, lo1);
        *(uint32_t*)(CtxH + row1 * HID + col) = pk2(h0, h1);
        *(uint32_t*)(CtxL + row1 * HID + col) = pk2(lo0, lo1);
    }
}

// ---------------------------------------------------------------------------
extern "C" void kernel_launch(void* const* d_in, const int* in_sizes, int n_in,
                              void* d_out, int out_size)
{
    const float* X  = (const float*)d_in[0];
    const float* Wq = (const float*)d_in[1];
    const float* bq = (const float*)d_in[2];
    const float* Wk = (const float*)d_in[3];
    const float* bk = (const float*)d_in[4];
    const float* Wv = (const float*)d_in[5];
    const float* bv = (const float*)d_in[6];
    const float* Wo = (const float*)d_in[7];
    const float* bo = (const float*)d_in[8];
    float* out = (float*)d_out;

    __nv_bfloat16 *xh, *xl, *wqh, *wql, *wkh, *wkl, *wvh, *wvl, *woh, *wol;
    __nv_bfloat16 *qh, *ql, *kh, *kl, *vh, *vl, *cxh, *cxl;
    float *stab, *ctab;
    cudaGetSymbolAddress((void**)&xh,  g_xh);
    cudaGetSymbolAddress((void**)&xl,  g_xl);
    cudaGetSymbolAddress((void**)&wqh, g_wqh);
    cudaGetSymbolAddress((void**)&wql, g_wql);
    cudaGetSymbolAddress((void**)&wkh, g_wkh);
    cudaGetSymbolAddress((void**)&wkl, g_wkl);
    cudaGetSymbolAddress((void**)&wvh, g_wvh);
    cudaGetSymbolAddress((void**)&wvl, g_wvl);
    cudaGetSymbolAddress((void**)&woh, g_woh);
    cudaGetSymbolAddress((void**)&wol, g_wol);
    cudaGetSymbolAddress((void**)&qh,  g_qh);
    cudaGetSymbolAddress((void**)&ql,  g_ql);
    cudaGetSymbolAddress((void**)&kh,  g_kh);
    cudaGetSymbolAddress((void**)&kl,  g_kl);
    cudaGetSymbolAddress((void**)&vh,  g_vh);
    cudaGetSymbolAddress((void**)&vl,  g_vl);
    cudaGetSymbolAddress((void**)&cxh, g_cxh);
    cudaGetSymbolAddress((void**)&cxl, g_cxl);
    cudaGetSymbolAddress((void**)&stab, g_sin);
    cudaGetSymbolAddress((void**)&ctab, g_cos);

    cudaFuncSetAttribute(mma_gemm_qkv_kernel,
                         cudaFuncAttributeMaxDynamicSharedMemorySize, GSMEM);
    cudaFuncSetAttribute(mma_gemm_out_kernel,
                         cudaFuncAttributeMaxDynamicSharedMemorySize, GSMEM);
    cudaFuncSetAttribute(flash2_kernel,
                         cudaFuncAttributeMaxDynamicSharedMemorySize, FL2_SMEM);

    // 0) RoPE sin/cos table
    rope_table_kernel<<<SEQ * 64 / 256, 256>>>(stab, ctab);

    // 1) split X into bf16 hi/lo
    split_x_kernel<<<(int)(((size_t)M_ROWS * HID / 4) / 256), 256>>>(
        (const float4*)X, (uint2*)xh, (uint2*)xl);

    // 2) transpose + split weights
    {
        dim3 g(HID / 32, HID / 32), blk(32, 8);
        wtrans_kernel<<<g, blk>>>(Wq, wqh, wql);
        wtrans_kernel<<<g, blk>>>(Wk, wkh, wkl);
        wtrans_kernel<<<g, blk>>>(Wv, wvh, wvl);
        wtrans_kernel<<<g, blk>>>(Wo, woh, wol);
    }

    // 3) QKV projections + bias + RoPE -> split-bf16 q/k/v
    {
        dim3 grid(HID / 128, M_ROWS / 128, 3);
        mma_gemm_qkv_kernel<<<grid, 256, GSMEM>>>(
            xh, xl, wqh, wql, wkh, wkl, wvh, wvl, bq, bk, bv,
            qh, ql, kh, kl, vh, vl, stab, ctab);
    }

    // 4) flash attention (tensor cores) -> split-bf16 context
    {
        dim3 grid(SEQ / BR, BATCH * NH);
        flash2_kernel<<<grid, 256, FL2_SMEM>>>(qh, ql, kh, kl, vh, vl, cxh, cxl);
    }

    // 5) output projection + bias -> out
    {
        dim3 grid(HID / 128, M_ROWS / 128);
        mma_gemm_out_kernel<<<grid, 256, GSMEM>>>(cxh, cxl, woh, wol, bo, out);
    }
}